// round 9
// baseline (speedup 1.0000x reference)
#include <cuda_runtime.h>
#include <cuda_fp16.h>
#include <math.h>
#include <stdint.h>

#define N_TOK 32768
#define M_CODE 4096
#define D_DIM 256
#define NT 128                        // codes per tile
#define CT_COUNT (M_CODE / NT)        // 32
#define CHUNKS (CT_COUNT * 8)         // 256 chunks of 32 k

// ---------------- smem layout (bytes) ----------------
#define A_PITCH 264                    // halves per row (256 + 8 pad)
#define A_SPLIT 67584                  // 128 * 264 * 2
#define SM_A    0                      // [2 splits][128 rows][264 halves]
#define SM_B    135168                 // per-warp private slices
#define BW_WARP 10240                  // bytes per warp (2 buf x 2 split x 2560)
#define BW_BUF  5120                   // per buffer within warp
#define BW_SPLIT 2560                  // per split within buffer (32 rows x 80B)
#define B_PITCH 40                     // halves per row (32 + 8 pad)
#define SM_FIDX 217088                 // 128 ints
#define SMEM_TOTAL 217600

__device__ float g_e2[M_CODE];
__device__ int   g_counts[M_CODE];
__device__ float g_loss_sum;
__device__ __align__(16) __half g_eh[M_CODE * D_DIM];
__device__ __align__(16) __half g_el[M_CODE * D_DIM];

// ---------------------------- helpers ----------------------------------
__device__ __forceinline__ uint32_t smem_u32(const void* p) {
    uint32_t a;
    asm("{ .reg .u64 t; cvta.to.shared.u64 t, %1; cvt.u32.u64 %0, t; }"
        : "=r"(a) : "l"(p));
    return a;
}
__device__ __forceinline__ void ldsm_x4(uint32_t& r0, uint32_t& r1,
                                        uint32_t& r2, uint32_t& r3, uint32_t a) {
    asm volatile("ldmatrix.sync.aligned.m8n8.x4.shared.b16 {%0,%1,%2,%3}, [%4];"
                 : "=r"(r0), "=r"(r1), "=r"(r2), "=r"(r3) : "r"(a));
}
__device__ __forceinline__ void cp16(uint32_t dst, const void* src) {
    asm volatile("cp.async.cg.shared.global [%0], [%1], 16;"
                 :: "r"(dst), "l"(src) : "memory");
}
__device__ __forceinline__ void cp_commit() {
    asm volatile("cp.async.commit_group;" ::: "memory");
}
__device__ __forceinline__ void cp_wait1() {
    asm volatile("cp.async.wait_group 1;" ::: "memory");
}
__device__ __forceinline__ void mma16816(float* c, const uint32_t* a, const uint32_t* b) {
    asm volatile(
        "mma.sync.aligned.m16n8k16.row.col.f32.f16.f16.f32 "
        "{%0,%1,%2,%3}, {%4,%5,%6,%7}, {%8,%9}, {%0,%1,%2,%3};"
        : "+f"(c[0]), "+f"(c[1]), "+f"(c[2]), "+f"(c[3])
        : "r"(a[0]), "r"(a[1]), "r"(a[2]), "r"(a[3]), "r"(b[0]), "r"(b[1]));
}

// ----------------------------- small kernels --------------------------------
__global__ void vq_init_kernel() {
    int t = blockIdx.x * blockDim.x + threadIdx.x;
    if (t < M_CODE) g_counts[t] = 0;
    if (t == 0) g_loss_sum = 0.0f;
}
__global__ void vq_e2_kernel(const float* __restrict__ embed) {
    int m = blockIdx.x * blockDim.x + threadIdx.x;
    if (m >= M_CODE) return;
    const float4* row = reinterpret_cast<const float4*>(embed + (size_t)m * D_DIM);
    float s = 0.0f;
#pragma unroll
    for (int i = 0; i < D_DIM / 4; i++) {
        float4 v = row[i];
        s += v.x * v.x + v.y * v.y + v.z * v.z + v.w * v.w;
    }
    g_e2[m] = s;
}
__global__ void vq_split_kernel(const float* __restrict__ embed) {
    int i = blockIdx.x * blockDim.x + threadIdx.x;   // one float4 each
    if (i >= M_CODE * D_DIM / 4) return;
    float4 v = reinterpret_cast<const float4*>(embed)[i];
    __half hx = __float2half_rn(v.x), hy = __float2half_rn(v.y);
    __half hz = __float2half_rn(v.z), hw = __float2half_rn(v.w);
    __half lx = __float2half_rn(v.x - __half2float(hx));
    __half ly = __float2half_rn(v.y - __half2float(hy));
    __half lz = __float2half_rn(v.z - __half2float(hz));
    __half lw = __float2half_rn(v.w - __half2float(hw));
    half2* ph = reinterpret_cast<half2*>(g_eh);
    half2* pl = reinterpret_cast<half2*>(g_el);
    ph[i * 2 + 0] = __halves2half2(hx, hy);
    ph[i * 2 + 1] = __halves2half2(hz, hw);
    pl[i * 2 + 0] = __halves2half2(lx, ly);
    pl[i * 2 + 1] = __halves2half2(lz, lw);
}

// ------------------------------ main kernel ---------------------------------
__global__ __launch_bounds__(256, 1)
void vq_main_kernel(const float* __restrict__ x,
                    const float* __restrict__ embed,
                    float* __restrict__ quant_out,
                    float* __restrict__ idx_out) {
    extern __shared__ char smem[];
    const uint32_t sb = smem_u32(smem);
    const int tid = threadIdx.x;
    const int lane = tid & 31;
    const int wid = tid >> 5;
    const int wm = wid >> 2;            // 0..1: rows wm*64 .. +64
    const int wn = wid & 3;             // 0..3: cols wn*32 .. +32 (within tile)
    const int row0 = blockIdx.x * 128;

    int* fidx = (int*)(smem + SM_FIDX);
    const uint32_t wB = sb + SM_B + wid * BW_WARP;

    // ldmatrix per-lane address offsets (bytes)
    //  A .x4: m0=rows0-7/k0-7, m1=rows8-15/k0-7, m2=rows0-7/k8-15, m3=rows8-15/k8-15
    const uint32_t aOff = ((uint32_t)(lane & 15) * A_PITCH + ((lane >> 4) & 1) * 8) * 2;
    //  B .x4: m0=n0-7/k0-7, m1=n0-7/k8-15, m2=n8-15/k0-7, m3=n8-15/k8-15
    const uint32_t bOff = (((uint32_t)(lane >> 4) * 8 + (lane & 7)) * B_PITCH +
                           ((lane >> 3) & 1) * 8) * 2;

    // per-lane cp.async role: lane = code row within the warp's 32-col stripe
    const uint32_t cpDstHi = wB + lane * (B_PITCH * 2);

    // ---- per-warp prologue: async-load own B slice for chunk 0 ----
    {
        const int code = wn * 32 + lane;   // ct=0, kc=0
        const __half* srch = g_eh + (size_t)code * D_DIM;
        const __half* srcl = g_el + (size_t)code * D_DIM;
#pragma unroll
        for (int j = 0; j < 4; j++) cp16(cpDstHi + j * 16, srch + j * 8);
#pragma unroll
        for (int j = 0; j < 4; j++) cp16(cpDstHi + BW_SPLIT + j * 16, srcl + j * 8);
        cp_commit();
    }

    // ---- stage x: split to fp16 hi/lo into smem [-2*x] ----
    for (int i = tid; i < 128 * 64; i += 256) {     // 8192 float4
        int row = i >> 6;
        int kq = (i & 63) << 2;
        float4 v = *(const float4*)(x + (size_t)(row0 + row) * D_DIM + kq);
        float ax = -2.0f * v.x, ay = -2.0f * v.y, az = -2.0f * v.z, aw = -2.0f * v.w;
        __half hx = __float2half_rn(ax), hy = __float2half_rn(ay);
        __half hz = __float2half_rn(az), hw = __float2half_rn(aw);
        __half lx = __float2half_rn(ax - __half2float(hx));
        __half ly = __float2half_rn(ay - __half2float(hy));
        __half lz = __float2half_rn(az - __half2float(hz));
        __half lw = __float2half_rn(aw - __half2float(hw));
        half2* dh = (half2*)(smem + SM_A + (size_t)(row * A_PITCH + kq) * 2);
        half2* dl = (half2*)(smem + SM_A + A_SPLIT + (size_t)(row * A_PITCH + kq) * 2);
        dh[0] = __halves2half2(hx, hy);
        dh[1] = __halves2half2(hz, hw);
        dl[0] = __halves2half2(lx, ly);
        dl[1] = __halves2half2(lz, lw);
    }
    __syncthreads();    // the ONLY pre-loop barrier: A tile visible to all warps

    float acc[4][4][4];        // [mt][nt][quad]
    float e2r[8];
    float bv[8];
    int bi[8];
#pragma unroll
    for (int s = 0; s < 8; s++) { bv[s] = 3.4e38f; bi[s] = 0; }

    // ======== barrier-free mainloop: warps fully decoupled ========
    for (int c = 0; c < CHUNKS; c++) {
        const int ct = c >> 3, kc = c & 7, buf = c & 1;

        // per-warp prefetch of chunk c+1 into own slice (other buffer)
        if (c + 1 < CHUNKS) {
            const int nct = (c + 1) >> 3, nkc = (c + 1) & 7, nbuf = (c + 1) & 1;
            const int code = nct * NT + wn * 32 + lane;
            const __half* srch = g_eh + (size_t)code * D_DIM + nkc * 32;
            const __half* srcl = g_el + (size_t)code * D_DIM + nkc * 32;
            uint32_t dst = cpDstHi + nbuf * BW_BUF;
#pragma unroll
            for (int j = 0; j < 4; j++) cp16(dst + j * 16, srch + j * 8);
#pragma unroll
            for (int j = 0; j < 4; j++) cp16(dst + BW_SPLIT + j * 16, srcl + j * 8);
        }
        cp_commit();
        cp_wait1();        // chunk c's slice now resident (per-thread ordering)

        if (kc == 0) {
#pragma unroll
            for (int mt = 0; mt < 4; mt++)
#pragma unroll
                for (int nt = 0; nt < 4; nt++)
#pragma unroll
                    for (int q = 0; q < 4; q++) acc[mt][nt][q] = 0.0f;
#pragma unroll
            for (int nt = 0; nt < 4; nt++)
#pragma unroll
                for (int q = 0; q < 2; q++)
                    e2r[nt * 2 + q] =
                        __ldg(&g_e2[ct * NT + wn * 32 + nt * 8 + (lane & 3) * 2 + q]);
        }

        // ---- compute: 2 k-steps of 16 ----
#pragma unroll
        for (int ks = 0; ks < 2; ks++) {
            const uint32_t kk0 = (kc * 32 + ks * 16) * 2;   // A k byte offset
            const uint32_t kl0 = (ks * 16) * 2;             // B k byte offset

            // B fragments: [nt][split][reg], 2 ldmatrix.x4 per split (32 cols)
            uint32_t b[4][2][2];
#pragma unroll
            for (int s = 0; s < 2; s++) {
                uint32_t base = wB + buf * BW_BUF + s * BW_SPLIT + bOff + kl0;
                ldsm_x4(b[0][s][0], b[0][s][1], b[1][s][0], b[1][s][1], base);
                ldsm_x4(b[2][s][0], b[2][s][1], b[3][s][0], b[3][s][1],
                        base + 16 * B_PITCH * 2);
            }

            uint32_t a[4][4];
            // --- a = A_hi; sweeps hh then hl (a reused) ---
            {
                uint32_t base = sb + SM_A + aOff + kk0 + wm * (64 * A_PITCH * 2);
#pragma unroll
                for (int mt = 0; mt < 4; mt++)
                    ldsm_x4(a[mt][0], a[mt][1], a[mt][2], a[mt][3],
                            base + mt * (16 * A_PITCH * 2));
            }
#pragma unroll
            for (int mt = 0; mt < 4; mt++)
#pragma unroll
                for (int nt = 0; nt < 4; nt++)
                    mma16816(acc[mt][nt], a[mt], b[nt][0]);
#pragma unroll
            for (int mt = 0; mt < 4; mt++)
#pragma unroll
                for (int nt = 0; nt < 4; nt++)
                    mma16816(acc[mt][nt], a[mt], b[nt][1]);
            // --- a = A_lo; sweep lh ---
            {
                uint32_t base = sb + SM_A + A_SPLIT + aOff + kk0 + wm * (64 * A_PITCH * 2);
#pragma unroll
                for (int mt = 0; mt < 4; mt++)
                    ldsm_x4(a[mt][0], a[mt][1], a[mt][2], a[mt][3],
                            base + mt * (16 * A_PITCH * 2));
            }
#pragma unroll
            for (int mt = 0; mt < 4; mt++)
#pragma unroll
                for (int nt = 0; nt < 4; nt++)
                    mma16816(acc[mt][nt], a[mt], b[nt][0]);
        }

        // ---- epilogue of this code tile: fold e2, running argmin ----
        if (kc == 7) {
#pragma unroll
            for (int mt = 0; mt < 4; mt++)
#pragma unroll
                for (int h = 0; h < 2; h++) {
                    int slot = mt * 2 + h;
#pragma unroll
                    for (int nt = 0; nt < 4; nt++)
#pragma unroll
                        for (int q = 0; q < 2; q++) {
                            float s = e2r[nt * 2 + q] + acc[mt][nt][h * 2 + q];
                            int col = ct * NT + wn * 32 + nt * 8 + (lane & 3) * 2 + q;
                            if (s < bv[slot]) { bv[slot] = s; bi[slot] = col; }
                        }
                }
        }
    }

    // ---- cross-thread argmin reduce (reuse B smem region) ----
    __syncthreads();
    float* redv = (float*)(smem + SM_B);
    int*   redi = (int*)(smem + SM_B + 8192);
#pragma unroll
    for (int slot = 0; slot < 8; slot++) {
        int mt = slot >> 1, h = slot & 1;
        int row_local = wm * 64 + mt * 16 + h * 8 + (lane >> 2);
        int j = wn * 4 + (lane & 3);
        redv[row_local * 16 + j] = bv[slot];
        redi[row_local * 16 + j] = bi[slot];
    }
    __syncthreads();

    if (tid < 128) {
        float bvv = 3.4e38f;
        int bii = M_CODE;
#pragma unroll
        for (int j = 0; j < 16; j++) {
            float v = redv[tid * 16 + j];
            int i = redi[tid * 16 + j];
            if (v < bvv || (v == bvv && i < bii)) { bvv = v; bii = i; }
        }
        fidx[tid] = bii;
        idx_out[row0 + tid] = (float)bii;
        atomicAdd(&g_counts[bii], 1);
    }
    __syncthreads();

    // ---- gather quantized rows + loss partial ----
    float lsum = 0.0f;
    for (int e = tid; e < 128 * D_DIM; e += 256) {
        int r = e >> 8, k = e & 255;
        float q = embed[(size_t)fidx[r] * D_DIM + k];
        float xv = x[(size_t)(row0 + r) * D_DIM + k];
        quant_out[(size_t)(row0 + r) * D_DIM + k] = q;
        float dd = q - xv;
        lsum += dd * dd;
    }
    float* lred = (float*)(smem + SM_B + 16384);
    lred[tid] = lsum;
    __syncthreads();
#pragma unroll
    for (int s = 128; s > 0; s >>= 1) {
        if (tid < s) lred[tid] += lred[tid + s];
        __syncthreads();
    }
    if (tid == 0) atomicAdd(&g_loss_sum, lred[0]);
}

// ------------------------------ finalize -------------------------------------
__global__ void vq_finalize_kernel(float* __restrict__ loss_out,
                                   float* __restrict__ perp_out) {
    __shared__ float hred[256];
    int tid = threadIdx.x;
    float h = 0.0f;
    for (int m = tid; m < M_CODE; m += 256) {
        float p = (float)g_counts[m] * (1.0f / (float)N_TOK);
        h += p * logf(p + 1e-10f);
    }
    hred[tid] = h;
    __syncthreads();
#pragma unroll
    for (int s = 128; s > 0; s >>= 1) {
        if (tid < s) hred[tid] += hred[tid + s];
        __syncthreads();
    }
    if (tid == 0) {
        *loss_out = 1.25f * g_loss_sum / (float)((size_t)N_TOK * D_DIM);
        *perp_out = expf(-hred[0]);
    }
}

// ------------------------------ launch ---------------------------------------
extern "C" void kernel_launch(void* const* d_in, const int* in_sizes, int n_in,
                              void* d_out, int out_size) {
    const float* x = (const float*)d_in[0];      // [N, D]
    const float* embed = (const float*)d_in[1];  // [M, D]

    float* out = (float*)d_out;
    float* quant = out;
    float* idxp  = out + (size_t)N_TOK * D_DIM;
    float* lossp = idxp + N_TOK;
    float* perpp = lossp + 1;

    cudaFuncSetAttribute(vq_main_kernel,
                         cudaFuncAttributeMaxDynamicSharedMemorySize, SMEM_TOTAL);

    vq_init_kernel<<<(M_CODE + 255) / 256, 256>>>();
    vq_e2_kernel<<<(M_CODE + 255) / 256, 256>>>(embed);
    vq_split_kernel<<<(M_CODE * D_DIM / 4 + 255) / 256, 256>>>(embed);
    vq_main_kernel<<<N_TOK / 128, 256, SMEM_TOTAL>>>(x, embed, quant, idxp);
    vq_finalize_kernel<<<1, 256>>>(lossp, perpp);
}

// round 10
// speedup vs baseline: 1.0648x; 1.0648x over previous
#include <cuda_runtime.h>
#include <cuda_fp16.h>
#include <math.h>
#include <stdint.h>

#define N_TOK 32768
#define M_CODE 4096
#define D_DIM 256
#define M_TILE 64                     // tokens per CTA
#define NT 128                        // codes per tile
#define CT_COUNT (M_CODE / NT)        // 32
#define CHUNKS (CT_COUNT * 8)         // 256 chunks of 32 k

// ---------------- smem layout (bytes) ----------------
#define A_PITCH 264                    // halves per row (256 + 8 pad)
#define A_SPLIT 33792                  // 64 * 264 * 2
#define SM_A    0                      // [2 splits][64 rows][264 halves]
#define SM_B    67584                  // per-warp private slices
#define BW_WARP 5120                   // bytes per warp (2 buf x 2 split x 1280)
#define BW_BUF  2560                   // per buffer within warp
#define BW_SPLIT 1280                  // per split within buffer (16 rows x 80B)
#define B_PITCH 40                     // halves per row (32 + 8 pad)
#define SM_FIDX 108544                 // 64 ints
#define SMEM_TOTAL 109056

__device__ float g_e2[M_CODE];
__device__ int   g_counts[M_CODE];
__device__ float g_loss_sum;
__device__ __align__(16) __half g_eh[M_CODE * D_DIM];
__device__ __align__(16) __half g_el[M_CODE * D_DIM];

// ---------------------------- helpers ----------------------------------
__device__ __forceinline__ uint32_t smem_u32(const void* p) {
    uint32_t a;
    asm("{ .reg .u64 t; cvta.to.shared.u64 t, %1; cvt.u32.u64 %0, t; }"
        : "=r"(a) : "l"(p));
    return a;
}
__device__ __forceinline__ void ldsm_x4(uint32_t& r0, uint32_t& r1,
                                        uint32_t& r2, uint32_t& r3, uint32_t a) {
    asm volatile("ldmatrix.sync.aligned.m8n8.x4.shared.b16 {%0,%1,%2,%3}, [%4];"
                 : "=r"(r0), "=r"(r1), "=r"(r2), "=r"(r3) : "r"(a));
}
__device__ __forceinline__ void cp16(uint32_t dst, const void* src) {
    asm volatile("cp.async.cg.shared.global [%0], [%1], 16;"
                 :: "r"(dst), "l"(src) : "memory");
}
__device__ __forceinline__ void cp_commit() {
    asm volatile("cp.async.commit_group;" ::: "memory");
}
__device__ __forceinline__ void cp_wait1() {
    asm volatile("cp.async.wait_group 1;" ::: "memory");
}
__device__ __forceinline__ void mma16816(float* c, const uint32_t* a, const uint32_t* b) {
    asm volatile(
        "mma.sync.aligned.m16n8k16.row.col.f32.f16.f16.f32 "
        "{%0,%1,%2,%3}, {%4,%5,%6,%7}, {%8,%9}, {%0,%1,%2,%3};"
        : "+f"(c[0]), "+f"(c[1]), "+f"(c[2]), "+f"(c[3])
        : "r"(a[0]), "r"(a[1]), "r"(a[2]), "r"(a[3]), "r"(b[0]), "r"(b[1]));
}

// ----------------------------- small kernels --------------------------------
__global__ void vq_init_kernel() {
    int t = blockIdx.x * blockDim.x + threadIdx.x;
    if (t < M_CODE) g_counts[t] = 0;
    if (t == 0) g_loss_sum = 0.0f;
}
__global__ void vq_e2_kernel(const float* __restrict__ embed) {
    int m = blockIdx.x * blockDim.x + threadIdx.x;
    if (m >= M_CODE) return;
    const float4* row = reinterpret_cast<const float4*>(embed + (size_t)m * D_DIM);
    float s = 0.0f;
#pragma unroll
    for (int i = 0; i < D_DIM / 4; i++) {
        float4 v = row[i];
        s += v.x * v.x + v.y * v.y + v.z * v.z + v.w * v.w;
    }
    g_e2[m] = s;
}
__global__ void vq_split_kernel(const float* __restrict__ embed) {
    int i = blockIdx.x * blockDim.x + threadIdx.x;   // one float4 each
    if (i >= M_CODE * D_DIM / 4) return;
    float4 v = reinterpret_cast<const float4*>(embed)[i];
    __half hx = __float2half_rn(v.x), hy = __float2half_rn(v.y);
    __half hz = __float2half_rn(v.z), hw = __float2half_rn(v.w);
    __half lx = __float2half_rn(v.x - __half2float(hx));
    __half ly = __float2half_rn(v.y - __half2float(hy));
    __half lz = __float2half_rn(v.z - __half2float(hz));
    __half lw = __float2half_rn(v.w - __half2float(hw));
    half2* ph = reinterpret_cast<half2*>(g_eh);
    half2* pl = reinterpret_cast<half2*>(g_el);
    ph[i * 2 + 0] = __halves2half2(hx, hy);
    ph[i * 2 + 1] = __halves2half2(hz, hw);
    pl[i * 2 + 0] = __halves2half2(lx, ly);
    pl[i * 2 + 1] = __halves2half2(lz, lw);
}

// ------------------------------ main kernel ---------------------------------
__global__ __launch_bounds__(256, 2)
void vq_main_kernel(const float* __restrict__ x,
                    const float* __restrict__ embed,
                    float* __restrict__ quant_out,
                    float* __restrict__ idx_out) {
    extern __shared__ char smem[];
    const uint32_t sb = smem_u32(smem);
    const int tid = threadIdx.x;
    const int lane = tid & 31;
    const int wid = tid >> 5;            // warp owns column stripe wid*16..+16
    const int row0 = blockIdx.x * M_TILE;

    int* fidx = (int*)(smem + SM_FIDX);
    const uint32_t wB = sb + SM_B + wid * BW_WARP;

    // ldmatrix per-lane address offsets (bytes)
    const uint32_t aOff = ((uint32_t)(lane & 15) * A_PITCH + ((lane >> 4) & 1) * 8) * 2;
    const uint32_t bOff = (((uint32_t)(lane >> 4) * 8 + (lane & 7)) * B_PITCH +
                           ((lane >> 3) & 1) * 8) * 2;

    // per-lane cp.async role: lane&15 = code row within stripe, lane>>4 = split
    const int cpRow = lane & 15;
    const int cpSplit = lane >> 4;
    const __half* cpSrcBase = (cpSplit ? g_el : g_eh);
    const uint32_t cpDstBase = wB + cpSplit * BW_SPLIT + cpRow * (B_PITCH * 2);

    // ---- per-warp prologue: async-load own B slice for chunk 0 ----
    {
        const __half* src = cpSrcBase + (size_t)(wid * 16 + cpRow) * D_DIM;  // ct=0,kc=0
#pragma unroll
        for (int j = 0; j < 4; j++) cp16(cpDstBase + j * 16, src + j * 8);
        cp_commit();
    }

    // ---- stage x: split to fp16 hi/lo into smem [-2*x] ----
    for (int i = tid; i < M_TILE * 64; i += 256) {     // 4096 float4
        int row = i >> 6;
        int kq = (i & 63) << 2;
        float4 v = *(const float4*)(x + (size_t)(row0 + row) * D_DIM + kq);
        float ax = -2.0f * v.x, ay = -2.0f * v.y, az = -2.0f * v.z, aw = -2.0f * v.w;
        __half hx = __float2half_rn(ax), hy = __float2half_rn(ay);
        __half hz = __float2half_rn(az), hw = __float2half_rn(aw);
        __half lx = __float2half_rn(ax - __half2float(hx));
        __half ly = __float2half_rn(ay - __half2float(hy));
        __half lz = __float2half_rn(az - __half2float(hz));
        __half lw = __float2half_rn(aw - __half2float(hw));
        half2* dh = (half2*)(smem + SM_A + (size_t)(row * A_PITCH + kq) * 2);
        half2* dl = (half2*)(smem + SM_A + A_SPLIT + (size_t)(row * A_PITCH + kq) * 2);
        dh[0] = __halves2half2(hx, hy);
        dh[1] = __halves2half2(hz, hw);
        dl[0] = __halves2half2(lx, ly);
        dl[1] = __halves2half2(lz, lw);
    }
    __syncthreads();    // the ONLY pre-loop barrier: A tile visible to all warps

    float acc[4][2][4];       // [mt][nt][quad]
    float e2r[4];
    float bv[8];
    int bi[8];
#pragma unroll
    for (int s = 0; s < 8; s++) { bv[s] = 3.4e38f; bi[s] = 0; }

    // ======== barrier-free mainloop: warps fully decoupled ========
    for (int c = 0; c < CHUNKS; c++) {
        const int ct = c >> 3, kc = c & 7, buf = c & 1;

        // per-warp prefetch of chunk c+1 into own slice (other buffer)
        if (c + 1 < CHUNKS) {
            const int nct = (c + 1) >> 3, nkc = (c + 1) & 7, nbuf = (c + 1) & 1;
            const __half* src = cpSrcBase +
                (size_t)(nct * NT + wid * 16 + cpRow) * D_DIM + nkc * 32;
            uint32_t dst = cpDstBase + nbuf * BW_BUF;
#pragma unroll
            for (int j = 0; j < 4; j++) cp16(dst + j * 16, src + j * 8);
        }
        cp_commit();
        cp_wait1();        // chunk c's slice now resident (per-thread ordering)

        if (kc == 0) {
#pragma unroll
            for (int mt = 0; mt < 4; mt++)
#pragma unroll
                for (int nt = 0; nt < 2; nt++)
#pragma unroll
                    for (int q = 0; q < 4; q++) acc[mt][nt][q] = 0.0f;
#pragma unroll
            for (int nt = 0; nt < 2; nt++)
#pragma unroll
                for (int q = 0; q < 2; q++)
                    e2r[nt * 2 + q] =
                        __ldg(&g_e2[ct * NT + wid * 16 + nt * 8 + (lane & 3) * 2 + q]);
        }

        // ---- compute: 2 k-steps of 16 ----
#pragma unroll
        for (int ks = 0; ks < 2; ks++) {
            const uint32_t kk0 = (kc * 32 + ks * 16) * 2;   // A k byte offset
            const uint32_t kl0 = (ks * 16) * 2;             // B k byte offset

            // B fragments: [nt][split][reg], 1 ldmatrix.x4 per split
            uint32_t b[2][2][2];
#pragma unroll
            for (int s = 0; s < 2; s++) {
                uint32_t base = wB + buf * BW_BUF + s * BW_SPLIT + bOff + kl0;
                ldsm_x4(b[0][s][0], b[0][s][1], b[1][s][0], b[1][s][1], base);
            }

            uint32_t a[4][4];
            // --- a = A_hi; sweeps hh then hl (a reused) ---
            {
                uint32_t base = sb + SM_A + aOff + kk0;
#pragma unroll
                for (int mt = 0; mt < 4; mt++)
                    ldsm_x4(a[mt][0], a[mt][1], a[mt][2], a[mt][3],
                            base + mt * (16 * A_PITCH * 2));
            }
#pragma unroll
            for (int mt = 0; mt < 4; mt++)
#pragma unroll
                for (int nt = 0; nt < 2; nt++)
                    mma16816(acc[mt][nt], a[mt], b[nt][0]);
#pragma unroll
            for (int mt = 0; mt < 4; mt++)
#pragma unroll
                for (int nt = 0; nt < 2; nt++)
                    mma16816(acc[mt][nt], a[mt], b[nt][1]);
            // --- a = A_lo; sweep lh ---
            {
                uint32_t base = sb + SM_A + A_SPLIT + aOff + kk0;
#pragma unroll
                for (int mt = 0; mt < 4; mt++)
                    ldsm_x4(a[mt][0], a[mt][1], a[mt][2], a[mt][3],
                            base + mt * (16 * A_PITCH * 2));
            }
#pragma unroll
            for (int mt = 0; mt < 4; mt++)
#pragma unroll
                for (int nt = 0; nt < 2; nt++)
                    mma16816(acc[mt][nt], a[mt], b[nt][0]);
        }

        // ---- epilogue of this code tile: fold e2, running argmin ----
        if (kc == 7) {
#pragma unroll
            for (int mt = 0; mt < 4; mt++)
#pragma unroll
                for (int h = 0; h < 2; h++) {
                    int slot = mt * 2 + h;
#pragma unroll
                    for (int nt = 0; nt < 2; nt++)
#pragma unroll
                        for (int q = 0; q < 2; q++) {
                            float s = e2r[nt * 2 + q] + acc[mt][nt][h * 2 + q];
                            int col = ct * NT + wid * 16 + nt * 8 + (lane & 3) * 2 + q;
                            if (s < bv[slot]) { bv[slot] = s; bi[slot] = col; }
                        }
                }
        }
    }

    // ---- cross-thread argmin reduce (reuse B smem region) ----
    __syncthreads();
    float* redv = (float*)(smem + SM_B);
    int*   redi = (int*)(smem + SM_B + 8192);
#pragma unroll
    for (int slot = 0; slot < 8; slot++) {
        int mt = slot >> 1, h = slot & 1;
        int row_local = mt * 16 + h * 8 + (lane >> 2);   // 0..63
        int j = wid * 4 + (lane & 3);                    // 0..31
        redv[row_local * 32 + j] = bv[slot];
        redi[row_local * 32 + j] = bi[slot];
    }
    __syncthreads();

    if (tid < M_TILE) {
        float bvv = 3.4e38f;
        int bii = M_CODE;
#pragma unroll
        for (int j = 0; j < 32; j++) {
            float v = redv[tid * 32 + j];
            int i = redi[tid * 32 + j];
            if (v < bvv || (v == bvv && i < bii)) { bvv = v; bii = i; }
        }
        fidx[tid] = bii;
        idx_out[row0 + tid] = (float)bii;
        atomicAdd(&g_counts[bii], 1);
    }
    __syncthreads();

    // ---- gather quantized rows + loss partial ----
    float lsum = 0.0f;
    for (int e = tid; e < M_TILE * D_DIM; e += 256) {
        int r = e >> 8, k = e & 255;
        float q = embed[(size_t)fidx[r] * D_DIM + k];
        float xv = x[(size_t)(row0 + r) * D_DIM + k];
        quant_out[(size_t)(row0 + r) * D_DIM + k] = q;
        float dd = q - xv;
        lsum += dd * dd;
    }
    float* lred = (float*)(smem + SM_B + 16384);
    lred[tid] = lsum;
    __syncthreads();
#pragma unroll
    for (int s = 128; s > 0; s >>= 1) {
        if (tid < s) lred[tid] += lred[tid + s];
        __syncthreads();
    }
    if (tid == 0) atomicAdd(&g_loss_sum, lred[0]);
}

// ------------------------------ finalize -------------------------------------
__global__ void vq_finalize_kernel(float* __restrict__ loss_out,
                                   float* __restrict__ perp_out) {
    __shared__ float hred[256];
    int tid = threadIdx.x;
    float h = 0.0f;
    for (int m = tid; m < M_CODE; m += 256) {
        float p = (float)g_counts[m] * (1.0f / (float)N_TOK);
        h += p * logf(p + 1e-10f);
    }
    hred[tid] = h;
    __syncthreads();
#pragma unroll
    for (int s = 128; s > 0; s >>= 1) {
        if (tid < s) hred[tid] += hred[tid + s];
        __syncthreads();
    }
    if (tid == 0) {
        *loss_out = 1.25f * g_loss_sum / (float)((size_t)N_TOK * D_DIM);
        *perp_out = expf(-hred[0]);
    }
}

// ------------------------------ launch ---------------------------------------
extern "C" void kernel_launch(void* const* d_in, const int* in_sizes, int n_in,
                              void* d_out, int out_size) {
    const float* x = (const float*)d_in[0];      // [N, D]
    const float* embed = (const float*)d_in[1];  // [M, D]

    float* out = (float*)d_out;
    float* quant = out;
    float* idxp  = out + (size_t)N_TOK * D_DIM;
    float* lossp = idxp + N_TOK;
    float* perpp = lossp + 1;

    cudaFuncSetAttribute(vq_main_kernel,
                         cudaFuncAttributeMaxDynamicSharedMemorySize, SMEM_TOTAL);

    vq_init_kernel<<<(M_CODE + 255) / 256, 256>>>();
    vq_e2_kernel<<<(M_CODE + 255) / 256, 256>>>(embed);
    vq_split_kernel<<<(M_CODE * D_DIM / 4 + 255) / 256, 256>>>(embed);
    vq_main_kernel<<<N_TOK / M_TILE, 256, SMEM_TOTAL>>>(x, embed, quant, idxp);
    vq_finalize_kernel<<<1, 256>>>(lossp, perpp);
}

// round 11
// speedup vs baseline: 1.2744x; 1.1968x over previous
#include <cuda_runtime.h>
#include <cuda_fp16.h>
#include <math.h>
#include <stdint.h>

#define N_TOK 32768
#define M_CODE 4096
#define D_DIM 256
#define M_TILE 128                    // tokens per CTA
#define NT 128                        // codes per tile
#define CT_COUNT (M_CODE / NT)        // 32
#define CHUNKS (CT_COUNT * 8)         // 256 chunks of 32 k
#define NTHREADS 512

// ---------------- smem layout (bytes) ----------------
#define A_PITCH 264                    // halves per row (256 + 8 pad)
#define A_SPLIT 67584                  // 128 * 264 * 2
#define SM_A    0                      // [2 splits][128 rows][264 halves]
#define SM_B    135168                 // 8 pair-shared slices
#define BW_SLICE 5120                  // per wn slice (2 buf x 2 split x 1280)
#define BW_BUF  2560                   // per buffer within slice
#define BW_SPLIT 1280                  // per split within buffer (16 rows x 80B)
#define B_PITCH 40                     // halves per row (32 + 8 pad)
#define SM_FIDX 176128                 // 128 ints
#define SMEM_TOTAL 176640

__device__ float g_e2[M_CODE];
__device__ int   g_counts[M_CODE];
__device__ float g_loss_sum;
__device__ __align__(16) __half g_eh[M_CODE * D_DIM];
__device__ __align__(16) __half g_el[M_CODE * D_DIM];

// ---------------------------- helpers ----------------------------------
__device__ __forceinline__ uint32_t smem_u32(const void* p) {
    uint32_t a;
    asm("{ .reg .u64 t; cvta.to.shared.u64 t, %1; cvt.u32.u64 %0, t; }"
        : "=r"(a) : "l"(p));
    return a;
}
__device__ __forceinline__ void ldsm_x4(uint32_t& r0, uint32_t& r1,
                                        uint32_t& r2, uint32_t& r3, uint32_t a) {
    asm volatile("ldmatrix.sync.aligned.m8n8.x4.shared.b16 {%0,%1,%2,%3}, [%4];"
                 : "=r"(r0), "=r"(r1), "=r"(r2), "=r"(r3) : "r"(a));
}
__device__ __forceinline__ void cp16(uint32_t dst, const void* src) {
    asm volatile("cp.async.cg.shared.global [%0], [%1], 16;"
                 :: "r"(dst), "l"(src) : "memory");
}
__device__ __forceinline__ void cp_commit() {
    asm volatile("cp.async.commit_group;" ::: "memory");
}
__device__ __forceinline__ void cp_wait1() {
    asm volatile("cp.async.wait_group 1;" ::: "memory");
}
__device__ __forceinline__ void bar_pair(int id) {
    asm volatile("bar.sync %0, 64;" :: "r"(id) : "memory");
}
__device__ __forceinline__ void mma16816(float* c, const uint32_t* a, const uint32_t* b) {
    asm volatile(
        "mma.sync.aligned.m16n8k16.row.col.f32.f16.f16.f32 "
        "{%0,%1,%2,%3}, {%4,%5,%6,%7}, {%8,%9}, {%0,%1,%2,%3};"
        : "+f"(c[0]), "+f"(c[1]), "+f"(c[2]), "+f"(c[3])
        : "r"(a[0]), "r"(a[1]), "r"(a[2]), "r"(a[3]), "r"(b[0]), "r"(b[1]));
}

// ----------------------------- small kernels --------------------------------
__global__ void vq_init_kernel() {
    int t = blockIdx.x * blockDim.x + threadIdx.x;
    if (t < M_CODE) g_counts[t] = 0;
    if (t == 0) g_loss_sum = 0.0f;
}
__global__ void vq_e2_kernel(const float* __restrict__ embed) {
    int m = blockIdx.x * blockDim.x + threadIdx.x;
    if (m >= M_CODE) return;
    const float4* row = reinterpret_cast<const float4*>(embed + (size_t)m * D_DIM);
    float s = 0.0f;
#pragma unroll
    for (int i = 0; i < D_DIM / 4; i++) {
        float4 v = row[i];
        s += v.x * v.x + v.y * v.y + v.z * v.z + v.w * v.w;
    }
    g_e2[m] = s;
}
__global__ void vq_split_kernel(const float* __restrict__ embed) {
    int i = blockIdx.x * blockDim.x + threadIdx.x;   // one float4 each
    if (i >= M_CODE * D_DIM / 4) return;
    float4 v = reinterpret_cast<const float4*>(embed)[i];
    __half hx = __float2half_rn(v.x), hy = __float2half_rn(v.y);
    __half hz = __float2half_rn(v.z), hw = __float2half_rn(v.w);
    __half lx = __float2half_rn(v.x - __half2float(hx));
    __half ly = __float2half_rn(v.y - __half2float(hy));
    __half lz = __float2half_rn(v.z - __half2float(hz));
    __half lw = __float2half_rn(v.w - __half2float(hw));
    half2* ph = reinterpret_cast<half2*>(g_eh);
    half2* pl = reinterpret_cast<half2*>(g_el);
    ph[i * 2 + 0] = __halves2half2(hx, hy);
    ph[i * 2 + 1] = __halves2half2(hz, hw);
    pl[i * 2 + 0] = __halves2half2(lx, ly);
    pl[i * 2 + 1] = __halves2half2(lz, lw);
}

// ------------------------------ main kernel ---------------------------------
__global__ __launch_bounds__(NTHREADS, 1)
void vq_main_kernel(const float* __restrict__ x,
                    const float* __restrict__ embed,
                    float* __restrict__ quant_out,
                    float* __restrict__ idx_out) {
    extern __shared__ char smem[];
    const uint32_t sb = smem_u32(smem);
    const int tid = threadIdx.x;
    const int lane = tid & 31;
    const int wid = tid >> 5;
    const int wn = wid & 7;              // col stripe wn*16 .. +16
    const int wm = wid >> 3;             // row half wm*64 .. +64
    const int row0 = blockIdx.x * M_TILE;
    const int barid = wn + 1;            // named barrier per wm-pair

    int* fidx = (int*)(smem + SM_FIDX);
    const uint32_t wB = sb + SM_B + wn * BW_SLICE;   // pair-shared slice

    // ldmatrix per-lane address offsets (bytes)
    const uint32_t aOff = ((uint32_t)(lane & 15) * A_PITCH + ((lane >> 4) & 1) * 8) * 2;
    const uint32_t bOff = (((uint32_t)(lane >> 4) * 8 + (lane & 7)) * B_PITCH +
                           ((lane >> 3) & 1) * 8) * 2;

    // cp.async role: this warp loads ONE split (wm) of the pair's slice.
    // lane>>1 = row (0..15), lane&1 = 32-byte half of the row.
    const int cpRow = lane >> 1;
    const int cpHalf = lane & 1;
    const __half* cpSrcBase = (wm ? g_el : g_eh);
    const uint32_t cpDstBase = wB + wm * BW_SPLIT + cpRow * (B_PITCH * 2) + cpHalf * 32;

    // ---- prologue: async-load pair slice for chunk 0 (this warp's split) ----
    {
        const __half* src = cpSrcBase + (size_t)(wn * 16 + cpRow) * D_DIM + cpHalf * 16;
        cp16(cpDstBase, src);
        cp16(cpDstBase + 16, src + 8);
        cp_commit();
    }

    // ---- stage x: split to fp16 hi/lo into smem [-2*x] ----
    for (int i = tid; i < M_TILE * 64; i += NTHREADS) {   // 8192 float4
        int row = i >> 6;
        int kq = (i & 63) << 2;
        float4 v = *(const float4*)(x + (size_t)(row0 + row) * D_DIM + kq);
        float ax = -2.0f * v.x, ay = -2.0f * v.y, az = -2.0f * v.z, aw = -2.0f * v.w;
        __half hx = __float2half_rn(ax), hy = __float2half_rn(ay);
        __half hz = __float2half_rn(az), hw = __float2half_rn(aw);
        __half lx = __float2half_rn(ax - __half2float(hx));
        __half ly = __float2half_rn(ay - __half2float(hy));
        __half lz = __float2half_rn(az - __half2float(hz));
        __half lw = __float2half_rn(aw - __half2float(hw));
        half2* dh = (half2*)(smem + SM_A + (size_t)(row * A_PITCH + kq) * 2);
        half2* dl = (half2*)(smem + SM_A + A_SPLIT + (size_t)(row * A_PITCH + kq) * 2);
        dh[0] = __halves2half2(hx, hy);
        dh[1] = __halves2half2(hz, hw);
        dl[0] = __halves2half2(lx, ly);
        dl[1] = __halves2half2(lz, lw);
    }
    __syncthreads();    // A tile visible to all warps

    float acc[4][2][4];       // [mt][nt][quad]
    float e2r[4];
    float bv[8];
    int bi[8];
#pragma unroll
    for (int s = 0; s < 8; s++) { bv[s] = 3.4e38f; bi[s] = 0; }

    // ======== mainloop: wm-pairs coupled by named barrier only ========
    for (int c = 0; c < CHUNKS; c++) {
        const int ct = c >> 3, kc = c & 7, buf = c & 1;

        // anti-dependency: both pair warps done reading buf^1 (chunk c-1)
        bar_pair(barid);

        // prefetch chunk c+1 (this warp's split only) into buf^1
        if (c + 1 < CHUNKS) {
            const int nct = (c + 1) >> 3, nkc = (c + 1) & 7, nbuf = (c + 1) & 1;
            const __half* src = cpSrcBase +
                (size_t)(nct * NT + wn * 16 + cpRow) * D_DIM + nkc * 32 + cpHalf * 16;
            uint32_t dst = cpDstBase + nbuf * BW_BUF;
            cp16(dst, src);
            cp16(dst + 16, src + 8);
        }
        cp_commit();
        cp_wait1();        // own writes for chunk c complete
        bar_pair(barid);   // partner's split for chunk c now visible

        if (kc == 0) {
#pragma unroll
            for (int mt = 0; mt < 4; mt++)
#pragma unroll
                for (int nt = 0; nt < 2; nt++)
#pragma unroll
                    for (int q = 0; q < 4; q++) acc[mt][nt][q] = 0.0f;
#pragma unroll
            for (int nt = 0; nt < 2; nt++)
#pragma unroll
                for (int q = 0; q < 2; q++)
                    e2r[nt * 2 + q] =
                        __ldg(&g_e2[ct * NT + wn * 16 + nt * 8 + (lane & 3) * 2 + q]);
        }

        // ---- compute: 2 k-steps of 16 ----
#pragma unroll
        for (int ks = 0; ks < 2; ks++) {
            const uint32_t kk0 = (kc * 32 + ks * 16) * 2;   // A k byte offset
            const uint32_t kl0 = (ks * 16) * 2;             // B k byte offset

            // B fragments: [nt][split][reg], 1 ldmatrix.x4 per split
            uint32_t b[2][2][2];
#pragma unroll
            for (int s = 0; s < 2; s++) {
                uint32_t base = wB + buf * BW_BUF + s * BW_SPLIT + bOff + kl0;
                ldsm_x4(b[0][s][0], b[0][s][1], b[1][s][0], b[1][s][1], base);
            }

            uint32_t a[4][4];
            // --- a = A_hi; sweeps hh then hl (a reused) ---
            {
                uint32_t base = sb + SM_A + aOff + kk0 + wm * (64 * A_PITCH * 2);
#pragma unroll
                for (int mt = 0; mt < 4; mt++)
                    ldsm_x4(a[mt][0], a[mt][1], a[mt][2], a[mt][3],
                            base + mt * (16 * A_PITCH * 2));
            }
#pragma unroll
            for (int mt = 0; mt < 4; mt++)
#pragma unroll
                for (int nt = 0; nt < 2; nt++)
                    mma16816(acc[mt][nt], a[mt], b[nt][0]);
#pragma unroll
            for (int mt = 0; mt < 4; mt++)
#pragma unroll
                for (int nt = 0; nt < 2; nt++)
                    mma16816(acc[mt][nt], a[mt], b[nt][1]);
            // --- a = A_lo; sweep lh ---
            {
                uint32_t base = sb + SM_A + A_SPLIT + aOff + kk0 + wm * (64 * A_PITCH * 2);
#pragma unroll
                for (int mt = 0; mt < 4; mt++)
                    ldsm_x4(a[mt][0], a[mt][1], a[mt][2], a[mt][3],
                            base + mt * (16 * A_PITCH * 2));
            }
#pragma unroll
            for (int mt = 0; mt < 4; mt++)
#pragma unroll
                for (int nt = 0; nt < 2; nt++)
                    mma16816(acc[mt][nt], a[mt], b[nt][0]);
        }

        // ---- epilogue of this code tile: fold e2, running argmin ----
        if (kc == 7) {
#pragma unroll
            for (int mt = 0; mt < 4; mt++)
#pragma unroll
                for (int h = 0; h < 2; h++) {
                    int slot = mt * 2 + h;
#pragma unroll
                    for (int nt = 0; nt < 2; nt++)
#pragma unroll
                        for (int q = 0; q < 2; q++) {
                            float s = e2r[nt * 2 + q] + acc[mt][nt][h * 2 + q];
                            int col = ct * NT + wn * 16 + nt * 8 + (lane & 3) * 2 + q;
                            if (s < bv[slot]) { bv[slot] = s; bi[slot] = col; }
                        }
                }
        }
    }

    // ---- cross-thread argmin reduce (reuse B smem region) ----
    __syncthreads();
    float* redv = (float*)(smem + SM_B);
    int*   redi = (int*)(smem + SM_B + 16384);
#pragma unroll
    for (int slot = 0; slot < 8; slot++) {
        int mt = slot >> 1, h = slot & 1;
        int row_local = wm * 64 + mt * 16 + h * 8 + (lane >> 2);   // 0..127
        int j = wn * 4 + (lane & 3);                               // 0..31
        redv[row_local * 32 + j] = bv[slot];
        redi[row_local * 32 + j] = bi[slot];
    }
    __syncthreads();

    if (tid < M_TILE) {
        float bvv = 3.4e38f;
        int bii = M_CODE;
#pragma unroll
        for (int j = 0; j < 32; j++) {
            float v = redv[tid * 32 + j];
            int i = redi[tid * 32 + j];
            if (v < bvv || (v == bvv && i < bii)) { bvv = v; bii = i; }
        }
        fidx[tid] = bii;
        idx_out[row0 + tid] = (float)bii;
        atomicAdd(&g_counts[bii], 1);
    }
    __syncthreads();

    // ---- gather quantized rows + loss partial ----
    float lsum = 0.0f;
    for (int e = tid; e < M_TILE * D_DIM; e += NTHREADS) {
        int r = e >> 8, k = e & 255;
        float q = embed[(size_t)fidx[r] * D_DIM + k];
        float xv = x[(size_t)(row0 + r) * D_DIM + k];
        quant_out[(size_t)(row0 + r) * D_DIM + k] = q;
        float dd = q - xv;
        lsum += dd * dd;
    }
    float* lred = (float*)(smem + SM_B + 32768);
    lred[tid] = lsum;
    __syncthreads();
#pragma unroll
    for (int s = NTHREADS / 2; s > 0; s >>= 1) {
        if (tid < s) lred[tid] += lred[tid + s];
        __syncthreads();
    }
    if (tid == 0) atomicAdd(&g_loss_sum, lred[0]);
}

// ------------------------------ finalize -------------------------------------
__global__ void vq_finalize_kernel(float* __restrict__ loss_out,
                                   float* __restrict__ perp_out) {
    __shared__ float hred[256];
    int tid = threadIdx.x;
    float h = 0.0f;
    for (int m = tid; m < M_CODE; m += 256) {
        float p = (float)g_counts[m] * (1.0f / (float)N_TOK);
        h += p * logf(p + 1e-10f);
    }
    hred[tid] = h;
    __syncthreads();
#pragma unroll
    for (int s = 128; s > 0; s >>= 1) {
        if (tid < s) hred[tid] += hred[tid + s];
        __syncthreads();
    }
    if (tid == 0) {
        *loss_out = 1.25f * g_loss_sum / (float)((size_t)N_TOK * D_DIM);
        *perp_out = expf(-hred[0]);
    }
}

// ------------------------------ launch ---------------------------------------
extern "C" void kernel_launch(void* const* d_in, const int* in_sizes, int n_in,
                              void* d_out, int out_size) {
    const float* x = (const float*)d_in[0];      // [N, D]
    const float* embed = (const float*)d_in[1];  // [M, D]

    float* out = (float*)d_out;
    float* quant = out;
    float* idxp  = out + (size_t)N_TOK * D_DIM;
    float* lossp = idxp + N_TOK;
    float* perpp = lossp + 1;

    cudaFuncSetAttribute(vq_main_kernel,
                         cudaFuncAttributeMaxDynamicSharedMemorySize, SMEM_TOTAL);

    vq_init_kernel<<<(M_CODE + 255) / 256, 256>>>();
    vq_e2_kernel<<<(M_CODE + 255) / 256, 256>>>(embed);
    vq_split_kernel<<<(M_CODE * D_DIM / 4 + 255) / 256, 256>>>(embed);
    vq_main_kernel<<<N_TOK / M_TILE, NTHREADS, SMEM_TOTAL>>>(x, embed, quant, idxp);
    vq_finalize_kernel<<<1, 256>>>(lossp, perpp);
}